// round 15
// baseline (speedup 1.0000x reference)
#include <cuda_runtime.h>
#include <cuda_fp16.h>
#include <math.h>
#include <cstdint>

// ---------------- problem constants ----------------
#define NNODES 50000
#define ECAP   1000000
#define SPLITA_BLOCKS 12500
#define WSCALE 3.4657359028f  // ln(32)

// ---------------- device scratch ----------------
__device__ __align__(16) __half g_zh[NNODES * 256];
__device__ float g_r2[NNODES * 40];
__device__ float g_elA[NNODES * 6];
__device__ float g_erA[NNODES * 6];
__device__ float g_elB[NNODES * 6];
__device__ float g_erB[NNODES * 6];
__device__ float g_inv[NNODES * 6];
__device__ int   g_deg[NNODES];
__device__ int   g_rowstart[NNODES + 1];
__device__ int   g_cursor[NNODES];
__device__ __align__(16) int g_srcs[ECAP];
__device__ __align__(16) __half g_wp[6 * ECAP];     // per-head weight planes
__device__ __align__(16) __half g_Ah[NNODES * 256];
__device__ __align__(16) __half g_Bh[256 * 256];
__device__ __align__(16) __half g_Bh2[64 * 256];

// ================= PTX helpers =================
__device__ __forceinline__ uint32_t smem_u32(const void* p) {
    uint32_t a;
    asm("{ .reg .u64 t; cvta.to.shared.u64 t, %1; cvt.u32.u64 %0, t; }" : "=r"(a) : "l"(p));
    return a;
}
__device__ __forceinline__ void cp16(uint32_t dst, const void* src, uint32_t srcsize) {
    asm volatile("cp.async.cg.shared.global [%0], [%1], 16, %2;"
                 :: "r"(dst), "l"(src), "r"(srcsize));
}
#define CP_COMMIT() asm volatile("cp.async.commit_group;" ::: "memory")
#define CP_WAIT(n)  asm volatile("cp.async.wait_group %0;" :: "n"(n) : "memory")
#define LDSM_X4(r0, r1, r2, r3, addr) \
    asm volatile("ldmatrix.sync.aligned.m8n8.x4.shared.b16 {%0,%1,%2,%3}, [%4];" \
        : "=r"(r0), "=r"(r1), "=r"(r2), "=r"(r3) : "r"(addr))
#define MMA_F16(acc, a, b) \
    asm volatile("mma.sync.aligned.m16n8k16.row.col.f32.f16.f16.f32 " \
        "{%0,%1,%2,%3}, {%4,%5,%6,%7}, {%8,%9}, {%0,%1,%2,%3};" \
        : "+f"((acc)[0]), "+f"((acc)[1]), "+f"((acc)[2]), "+f"((acc)[3]) \
        : "r"((a)[0]), "r"((a)[1]), "r"((a)[2]), "r"((a)[3]), "r"((b)[0]), "r"((b)[1]))

// ---------------- helpers ----------------
__device__ __forceinline__ void convBt_elem(const float* __restrict__ B,
                                            __half* __restrict__ out, int t, int Nn) {
    int nrow = t >> 8, k = t & 255;
    float x = (nrow < Nn) ? B[(size_t)k * Nn + nrow] : 0.f;
    out[t] = __float2half_rn(x);
}
__device__ __forceinline__ void resmean_elem(const float* __restrict__ resW2, int t) {
    int d = t >> 8, k = t & 255;
    float x = 0.f;
    if (d < 40) {
        float s_ = 0.f;
        #pragma unroll
        for (int h = 0; h < 6; ++h) s_ += resW2[(size_t)k * 240 + h * 40 + d];
        x = s_ * (1.0f / 6.0f);
    }
    g_Bh2[t] = __float2half_rn(x);
}

// ---------------- prep0 ----------------
__global__ void k_prep0(const float* __restrict__ feat, const float* __restrict__ W0,
                        const int* __restrict__ dst, int E) {
    int bx = blockIdx.x;
    if (bx < SPLITA_BLOCKS) {
        int i = bx * 256 + threadIdx.x;
        float4 v = reinterpret_cast<const float4*>(feat)[i];
        __half2 p0 = __floats2half2_rn(v.x, v.y);
        __half2 p1 = __floats2half2_rn(v.z, v.w);
        reinterpret_cast<uint2*>(g_Ah)[i] =
            make_uint2(*reinterpret_cast<uint32_t*>(&p0), *reinterpret_cast<uint32_t*>(&p1));
    } else if (bx < SPLITA_BLOCKS + 256) {
        int t = (bx - SPLITA_BLOCKS) * 256 + threadIdx.x;
        convBt_elem(W0, g_Bh, t, 256);
    } else {
        int e = (bx - SPLITA_BLOCKS - 256) * 256 + threadIdx.x;
        if (e < E) atomicAdd(&g_deg[dst[e]], 1);
    }
}

// ---------------- scan ----------------
__global__ void k_scan(int n, int E) {
    __shared__ int wsum[32];
    __shared__ int carry;
    int lane = threadIdx.x & 31, w = threadIdx.x >> 5;
    if (threadIdx.x == 0) carry = 0;
    __syncthreads();
    for (int base = 0; base < n; base += 1024) {
        int i = base + threadIdx.x;
        int v = (i < n) ? g_deg[i] : 0;
        int x = v;
        #pragma unroll
        for (int off = 1; off < 32; off <<= 1) {
            int t = __shfl_up_sync(0xffffffffu, x, off);
            if (lane >= off) x += t;
        }
        if (lane == 31) wsum[w] = x;
        __syncthreads();
        if (w == 0) {
            int y = wsum[lane];
            #pragma unroll
            for (int off = 1; off < 32; off <<= 1) {
                int t = __shfl_up_sync(0xffffffffu, y, off);
                if (lane >= off) y += t;
            }
            wsum[lane] = y;
        }
        __syncthreads();
        int incl = x + (w ? wsum[w - 1] : 0) + carry;
        int excl = incl - v;
        if (i < n) { g_rowstart[i] = excl; g_cursor[i] = excl; }
        __syncthreads();
        if (threadIdx.x == 1023) carry = incl;
        __syncthreads();
    }
    if (threadIdx.x == 0) g_rowstart[n] = E;
}

// ---------------- GEMM body (fp16 mma.sync, BM=64, 128 threads, 2-stage) ----------------
template <int BN>
__device__ __forceinline__ void gemm_load_stage(
    uint32_t sb, const __half* __restrict__ Ah, const __half* __restrict__ Bh,
    int m0, int n0, int M, int kb, int tid)
{
    #pragma unroll
    for (int it = 0; it < 4; ++it) {
        int idx = tid + it * 128;
        int row = idx >> 3, ch = idx & 7;
        uint32_t dst = sb + row * 128 + (((uint32_t)(ch ^ (row & 7))) << 4);
        const __half* src = Ah + (size_t)(m0 + row) * 256 + kb * 64 + ch * 8;
        cp16(dst, src, (m0 + row) < M ? 16u : 0u);
    }
    #pragma unroll
    for (int it = 0; it < (BN * 8) / 128; ++it) {
        int idx = tid + it * 128;
        int row = idx >> 3, ch = idx & 7;
        uint32_t dst = sb + 8192 + row * 128 + (((uint32_t)(ch ^ (row & 7))) << 4);
        const __half* src = Bh + (size_t)(n0 + row) * 256 + kb * 64 + ch * 8;
        cp16(dst, src, 16u);
    }
}

template <int MODE, int BN>
__device__ __forceinline__ void gemm_body(
    const __half* __restrict__ Ah, const __half* __restrict__ Bh,
    __half* __restrict__ Ch, float* __restrict__ Cf,
    const float* __restrict__ al, const float* __restrict__ ar,
    float* __restrict__ el, float* __restrict__ er,
    int M, int Nn, int H, int D, int m0, int n0)
{
    constexpr int NT = BN / 16;
    constexpr uint32_t STAGE = 8192u + (uint32_t)BN * 128u;
    extern __shared__ char smem[];
    const uint32_t sbase = smem_u32(smem);
    const int tid = threadIdx.x, wid = tid >> 5, lane = tid & 31;
    const int warp_m = wid & 1, warp_n = wid >> 1;

    float acc[2][NT][4];
    #pragma unroll
    for (int mt = 0; mt < 2; ++mt)
        #pragma unroll
        for (int nt = 0; nt < NT; ++nt)
            #pragma unroll
            for (int q = 0; q < 4; ++q) acc[mt][nt][q] = 0.f;

    const int rowA = warp_m * 32 + (lane & 15);
    const int rowB = warp_n * (BN / 2) + (lane & 7) + ((lane >> 4) << 3);
    const uint32_t rowAswz = (uint32_t)(rowA & 7);
    const uint32_t rowBswz = (uint32_t)(rowB & 7);
    const int halfA = lane >> 4;
    const int halfB = (lane >> 3) & 1;

    gemm_load_stage<BN>(sbase, Ah, Bh, m0, n0, M, 0, tid);
    CP_COMMIT();
    gemm_load_stage<BN>(sbase + STAGE, Ah, Bh, m0, n0, M, 1, tid);
    CP_COMMIT();

    #pragma unroll 1
    for (int kb = 0; kb < 4; ++kb) {
        if (kb < 3) { CP_WAIT(1); } else { CP_WAIT(0); }
        __syncthreads();
        const uint32_t sb = sbase + (kb & 1) * STAGE;
        #pragma unroll
        for (int s = 0; s < 4; ++s) {
            uint32_t a[2][4];
            uint32_t b[NT][2];
            const uint32_t offA = (((uint32_t)(s * 2 + halfA) ^ rowAswz) << 4);
            const uint32_t offB = (((uint32_t)(s * 2 + halfB) ^ rowBswz) << 4);
            #pragma unroll
            for (int mt = 0; mt < 2; ++mt) {
                uint32_t addr = sb + (uint32_t)(rowA + mt * 16) * 128 + offA;
                LDSM_X4(a[mt][0], a[mt][1], a[mt][2], a[mt][3], addr);
            }
            #pragma unroll
            for (int ntp = 0; ntp < NT / 2; ++ntp) {
                uint32_t addr = sb + 8192 + (uint32_t)(rowB + ntp * 16) * 128 + offB;
                LDSM_X4(b[2 * ntp][0], b[2 * ntp][1], b[2 * ntp + 1][0], b[2 * ntp + 1][1], addr);
            }
            #pragma unroll
            for (int mt = 0; mt < 2; ++mt)
                #pragma unroll
                for (int nt = 0; nt < NT; ++nt)
                    MMA_F16(acc[mt][nt], a[mt], b[nt]);
        }
        __syncthreads();
        if (kb < 2) {
            gemm_load_stage<BN>(sbase + (kb & 1) * STAGE, Ah, Bh, m0, n0, M, kb + 2, tid);
            CP_COMMIT();
        }
    }

    #pragma unroll
    for (int mt = 0; mt < 2; ++mt) {
        int row = m0 + warp_m * 32 + mt * 16 + (lane >> 2);
        #pragma unroll
        for (int nt = 0; nt < NT; ++nt) {
            int col = n0 + warp_n * (BN / 2) + nt * 8 + (lane & 3) * 2;
            if (col < Nn) {
                if (MODE != 0) {
                    if (row < M)
                        *reinterpret_cast<__half2*>(Ch + (size_t)row * Nn + col) =
                            __floats2half2_rn(acc[mt][nt][0], acc[mt][nt][1]);
                    if (row + 8 < M)
                        *reinterpret_cast<__half2*>(Ch + (size_t)(row + 8) * Nn + col) =
                            __floats2half2_rn(acc[mt][nt][2], acc[mt][nt][3]);
                } else {
                    if (row < M)
                        *reinterpret_cast<float2*>(Cf + (size_t)row * Nn + col) =
                            make_float2(acc[mt][nt][0], acc[mt][nt][1]);
                    if (row + 8 < M)
                        *reinterpret_cast<float2*>(Cf + (size_t)(row + 8) * Nn + col) =
                            make_float2(acc[mt][nt][2], acc[mt][nt][3]);
                }
            }
        }
    }

    if (MODE == 1) {
        const int h = (n0 + warp_n * 64) >> 6;
        float sl[2][2] = {}, sr[2][2] = {};
        #pragma unroll
        for (int nt = 0; nt < NT; ++nt) {
            int dloc = nt * 8 + (lane & 3) * 2;
            float2 av = __ldg(reinterpret_cast<const float2*>(al + h * 64 + dloc));
            float2 rv = __ldg(reinterpret_cast<const float2*>(ar + h * 64 + dloc));
            #pragma unroll
            for (int mt = 0; mt < 2; ++mt) {
                sl[mt][0] += acc[mt][nt][0] * av.x + acc[mt][nt][1] * av.y;
                sr[mt][0] += acc[mt][nt][0] * rv.x + acc[mt][nt][1] * rv.y;
                sl[mt][1] += acc[mt][nt][2] * av.x + acc[mt][nt][3] * av.y;
                sr[mt][1] += acc[mt][nt][2] * rv.x + acc[mt][nt][3] * rv.y;
            }
        }
        #pragma unroll
        for (int mt = 0; mt < 2; ++mt)
            #pragma unroll
            for (int rh = 0; rh < 2; ++rh) {
                float vl = sl[mt][rh], vr = sr[mt][rh];
                vl += __shfl_xor_sync(0xffffffffu, vl, 1);
                vl += __shfl_xor_sync(0xffffffffu, vl, 2);
                vr += __shfl_xor_sync(0xffffffffu, vr, 1);
                vr += __shfl_xor_sync(0xffffffffu, vr, 2);
                sl[mt][rh] = vl; sr[mt][rh] = vr;
            }
        if ((lane & 3) == 0) {
            #pragma unroll
            for (int mt = 0; mt < 2; ++mt)
                #pragma unroll
                for (int rh = 0; rh < 2; ++rh) {
                    int row = m0 + warp_m * 32 + mt * 16 + (lane >> 2) + rh * 8;
                    if (row < M) {
                        el[(size_t)row * H + h] = sl[mt][rh];
                        er[(size_t)row * H + h] = sr[mt][rh];
                    }
                }
        }
    } else if (MODE == 2) {
        const int colbase = n0 + warp_n * (BN / 2);
        if (colbase < Nn) {
            const int h0 = colbase / D;
            const int colend = (colbase + BN / 2 < Nn) ? (colbase + BN / 2) : Nn;
            const int hmax = (colend - 1) / D;
            float sl[2][2][3] = {}, sr[2][2][3] = {};
            #pragma unroll
            for (int nt = 0; nt < NT; ++nt) {
                int colg = colbase + nt * 8;
                if (colg < Nn) {
                    int h = colg / D;
                    int slot = h - h0;
                    if (slot > 2) slot = 2;
                    int d = colg - h * D + (lane & 3) * 2;
                    float2 av = __ldg(reinterpret_cast<const float2*>(al + h * D + d));
                    float2 rv = __ldg(reinterpret_cast<const float2*>(ar + h * D + d));
                    #pragma unroll
                    for (int mt = 0; mt < 2; ++mt) {
                        sl[mt][0][slot] += acc[mt][nt][0] * av.x + acc[mt][nt][1] * av.y;
                        sr[mt][0][slot] += acc[mt][nt][0] * rv.x + acc[mt][nt][1] * rv.y;
                        sl[mt][1][slot] += acc[mt][nt][2] * av.x + acc[mt][nt][3] * av.y;
                        sr[mt][1][slot] += acc[mt][nt][2] * rv.x + acc[mt][nt][3] * rv.y;
                    }
                }
            }
            #pragma unroll
            for (int mt = 0; mt < 2; ++mt)
                #pragma unroll
                for (int rh = 0; rh < 2; ++rh)
                    #pragma unroll
                    for (int sx = 0; sx < 3; ++sx) {
                        float vl = sl[mt][rh][sx], vr = sr[mt][rh][sx];
                        vl += __shfl_xor_sync(0xffffffffu, vl, 1);
                        vl += __shfl_xor_sync(0xffffffffu, vl, 2);
                        vr += __shfl_xor_sync(0xffffffffu, vr, 1);
                        vr += __shfl_xor_sync(0xffffffffu, vr, 2);
                        sl[mt][rh][sx] = vl; sr[mt][rh][sx] = vr;
                    }
            if ((lane & 3) == 0) {
                int nslots = hmax - h0 + 1;
                if (nslots > 3) nslots = 3;
                #pragma unroll
                for (int mt = 0; mt < 2; ++mt)
                    #pragma unroll
                    for (int rh = 0; rh < 2; ++rh) {
                        int row = m0 + warp_m * 32 + mt * 16 + (lane >> 2) + rh * 8;
                        if (row < M) {
                            for (int sx = 0; sx < nslots; ++sx) {
                                atomicAdd(&el[(size_t)row * H + h0 + sx], sl[mt][rh][sx]);
                                atomicAdd(&er[(size_t)row * H + h0 + sx], sr[mt][rh][sx]);
                            }
                        }
                    }
            }
        }
    }
}

#define GEMM_SMEM128 (2 * (8192 + 128 * 128))

// ---------------- GEMM launches ----------------
__global__ __launch_bounds__(128, 4) void k_gemm0(
    const __half* __restrict__ Ah, __half* __restrict__ Ch,
    const float* __restrict__ al, const float* __restrict__ ar,
    float* __restrict__ el, float* __restrict__ er, int M, int nGemm,
    const int* __restrict__ src, const int* __restrict__ dst, int E)
{
    int bx = blockIdx.x;
    if (bx < nGemm) {
        gemm_body<1, 128>(Ah, g_Bh, Ch, nullptr, al, ar, el, er,
                          M, 256, 4, 64, (bx >> 1) * 64, (bx & 1) * 128);
    } else {
        int e = (bx - nGemm) * 128 + threadIdx.x;
        if (e < E) {
            int p = atomicAdd(&g_cursor[dst[e]], 1);
            g_srcs[p] = src[e];
        }
    }
}

__global__ __launch_bounds__(128, 4) void k_gemm1(
    const __half* __restrict__ Ah, __half* __restrict__ Ch,
    const float* __restrict__ al, const float* __restrict__ ar,
    float* __restrict__ el, float* __restrict__ er, int M)
{
    int bx = blockIdx.x;
    gemm_body<1, 128>(Ah, g_Bh, Ch, nullptr, al, ar, el, er,
                      M, 256, 4, 64, (bx >> 1) * 64, (bx & 1) * 128);
}

__global__ __launch_bounds__(128, 4) void k_gemm2(
    const __half* __restrict__ Ah, __half* __restrict__ Ch, float* __restrict__ Cf,
    const float* __restrict__ al, const float* __restrict__ ar,
    float* __restrict__ el, float* __restrict__ er, int M, int nGemm)
{
    int bx = blockIdx.x;
    if (bx < nGemm) {
        gemm_body<2, 128>(Ah, g_Bh, Ch, nullptr, al, ar, el, er,
                          M, 240, 6, 40, (bx >> 1) * 64, (bx & 1) * 128);
    } else {
        gemm_body<0, 64>(Ah, g_Bh2, nullptr, Cf, nullptr, nullptr, nullptr, nullptr,
                         M, 40, 1, 64, (bx - nGemm) * 64, 0);
    }
}

// ---------------- edge-weight precompute: w planes + inverse denominators ----------------
template <int H>
__global__ __launch_bounds__(256) void k_wgt(
    const float* __restrict__ el, const float* __restrict__ er,
    float* __restrict__ inv, int n)
{
    int gw = (blockIdx.x * 256 + threadIdx.x) >> 5;
    if (gw >= n) return;
    int lane = threadIdx.x & 31;
    constexpr int LQ = 32 / H;               // edges per iteration
    int lq = lane / H, h = lane - lq * H;
    bool act = lq < LQ;
    int beg = g_rowstart[gw], end = g_rowstart[gw + 1];
    float erh = act ? __ldg(&er[gw * H + h]) : 0.f;
    float denom = 0.f;
    #pragma unroll 1
    for (int j = beg; j < end; j += LQ) {
        int slot = j + lq;
        if (act && slot < end) {
            int s = __ldg(&g_srcs[slot]);
            float e = __ldg(&el[s * H + h]) + erh;
            e = (e > 0.f) ? e : 0.2f * e;
            float w = __expf(e - WSCALE);
            __half hw = __float2half_rn(w);
            g_wp[(size_t)h * ECAP + slot] = hw;
            denom += __half2float(hw);
        }
    }
    if (H == 4) {
        denom += __shfl_xor_sync(0xffffffffu, denom, 4);
        denom += __shfl_xor_sync(0xffffffffu, denom, 8);
        denom += __shfl_xor_sync(0xffffffffu, denom, 16);
    } else {
        float t = denom;
        denom = 0.f;
        #pragma unroll
        for (int k = 0; k < 5; ++k)
            denom += __shfl_sync(0xffffffffu, t, h + k * H);
    }
    if (act && lq == 0) inv[gw * H + h] = 1.f / denom;
}

// ---------------- fp16 quad-tree accumulate ----------------
__device__ __forceinline__ void quad_acc(
    float2* accf, const uint4& q0, const uint4& q1, const uint4& q2, const uint4& q3,
    __half2 w0, __half2 w1, __half2 w2, __half2 w3)
{
    const __half2* z0 = reinterpret_cast<const __half2*>(&q0);
    const __half2* z1 = reinterpret_cast<const __half2*>(&q1);
    const __half2* z2 = reinterpret_cast<const __half2*>(&q2);
    const __half2* z3 = reinterpret_cast<const __half2*>(&q3);
    #pragma unroll
    for (int j = 0; j < 4; ++j) {
        __half2 t = __hadd2(__hadd2(__hmul2(w0, z0[j]), __hmul2(w1, z1[j])),
                            __hadd2(__hmul2(w2, z2[j]), __hmul2(w3, z3[j])));
        float2 tf = __half22float2(t);
        accf[j].x += tf.x;
        accf[j].y += tf.y;
    }
}
__device__ __forceinline__ void one_acc(float2* accf, const uint4& q, __half2 w)
{
    const __half2* z = reinterpret_cast<const __half2*>(&q);
    #pragma unroll
    for (int j = 0; j < 4; ++j) {
        float2 tf = __half22float2(__hmul2(w, z[j]));
        accf[j].x += tf.x;
        accf[j].y += tf.y;
    }
}

// ---------------- aggregation, layers 0/1 ----------------
template <bool RES>
__global__ __launch_bounds__(256) void k_agg256(
    const __half* __restrict__ zh, const float* __restrict__ inv,
    const float* __restrict__ bias,
    float* __restrict__ out, __half* __restrict__ oah, int n, int nAgg,
    const float* __restrict__ Wnext, int convN,
    const float* __restrict__ resW2,
    float* __restrict__ zel, float* __restrict__ zer, int n6)
{
    int bx = blockIdx.x;
    if (bx >= nAgg) {
        int t = bx - nAgg;
        if (t < 256) {
            convBt_elem(Wnext, g_Bh, t * 256 + threadIdx.x, convN);
        } else if (resW2 != nullptr && t < 320) {
            resmean_elem(resW2, (t - 256) * 256 + threadIdx.x);
        } else if (zel != nullptr) {
            int zoff = (resW2 != nullptr) ? 320 : 256;
            int i = (t - zoff) * 256 + threadIdx.x;
            if (i < n6) { zel[i] = 0.f; zer[i] = 0.f; }
        }
        return;
    }
    int gw = (bx * 256 + threadIdx.x) >> 5;
    if (gw >= n) return;
    int lane = threadIdx.x & 31;
    int beg = g_rowstart[gw], end = g_rowstart[gw + 1];
    int h = lane >> 3;
    const __half* wp = g_wp + (size_t)h * ECAP;
    int c0 = lane * 8;
    float2 accf[4] = {{0.f,0.f},{0.f,0.f},{0.f,0.f},{0.f,0.f}};
    int i = beg;
    // align to 4
    for (; i < end && (i & 3); ++i) {
        int s0 = __ldg(&g_srcs[i]);
        uint4 q0 = __ldg(reinterpret_cast<const uint4*>(zh + (size_t)s0 * 256 + c0));
        one_acc(accf, q0, __half2half2(__ldg(&wp[i])));
    }
    #pragma unroll 1
    for (; i + 4 <= end; i += 4) {
        int4 s4 = __ldg(reinterpret_cast<const int4*>(&g_srcs[i]));
        uint2 w4 = __ldg(reinterpret_cast<const uint2*>(&wp[i]));
        uint4 q0 = __ldg(reinterpret_cast<const uint4*>(zh + (size_t)s4.x * 256 + c0));
        uint4 q1 = __ldg(reinterpret_cast<const uint4*>(zh + (size_t)s4.y * 256 + c0));
        uint4 q2 = __ldg(reinterpret_cast<const uint4*>(zh + (size_t)s4.z * 256 + c0));
        uint4 q3 = __ldg(reinterpret_cast<const uint4*>(zh + (size_t)s4.w * 256 + c0));
        __half2 wa = *reinterpret_cast<__half2*>(&w4.x);
        __half2 wb = *reinterpret_cast<__half2*>(&w4.y);
        quad_acc(accf, q0, q1, q2, q3,
                 __half2half2(__low2half(wa)), __half2half2(__high2half(wa)),
                 __half2half2(__low2half(wb)), __half2half2(__high2half(wb)));
    }
    for (; i < end; ++i) {
        int s0 = __ldg(&g_srcs[i]);
        uint4 q0 = __ldg(reinterpret_cast<const uint4*>(zh + (size_t)s0 * 256 + c0));
        one_acc(accf, q0, __half2half2(__ldg(&wp[i])));
    }
    float invv = __ldg(&inv[gw * 4 + h]);
    const float4* bp = reinterpret_cast<const float4*>(bias + c0);
    float4 b0 = __ldg(bp), b1 = __ldg(bp + 1);
    float v[8];
    v[0] = fmaf(accf[0].x, invv, b0.x); v[1] = fmaf(accf[0].y, invv, b0.y);
    v[2] = fmaf(accf[1].x, invv, b0.z); v[3] = fmaf(accf[1].y, invv, b0.w);
    v[4] = fmaf(accf[2].x, invv, b1.x); v[5] = fmaf(accf[2].y, invv, b1.y);
    v[6] = fmaf(accf[3].x, invv, b1.z); v[7] = fmaf(accf[3].y, invv, b1.w);
    if (RES) {
        uint4 rq = *reinterpret_cast<const uint4*>(oah + (size_t)gw * 256 + c0);
        float2 r0 = __half22float2(*reinterpret_cast<__half2*>(&rq.x));
        float2 r1 = __half22float2(*reinterpret_cast<__half2*>(&rq.y));
        float2 r2 = __half22float2(*reinterpret_cast<__half2*>(&rq.z));
        float2 r3 = __half22float2(*reinterpret_cast<__half2*>(&rq.w));
        v[0] += r0.x; v[1] += r0.y; v[2] += r1.x; v[3] += r1.y;
        v[4] += r2.x; v[5] += r2.y; v[6] += r3.x; v[7] += r3.y;
    }
    #pragma unroll
    for (int j = 0; j < 8; ++j) v[j] = (v[j] > 0.f) ? v[j] : expm1f(v[j]);
    if (out != nullptr) {
        float4* op = reinterpret_cast<float4*>(out + (size_t)gw * 256 + c0);
        op[0] = make_float4(v[0], v[1], v[2], v[3]);
        op[1] = make_float4(v[4], v[5], v[6], v[7]);
    }
    __half2 p0 = __floats2half2_rn(v[0], v[1]);
    __half2 p1 = __floats2half2_rn(v[2], v[3]);
    __half2 p2 = __floats2half2_rn(v[4], v[5]);
    __half2 p3 = __floats2half2_rn(v[6], v[7]);
    *reinterpret_cast<uint4*>(oah + (size_t)gw * 256 + c0) =
        make_uint4(*reinterpret_cast<uint32_t*>(&p0), *reinterpret_cast<uint32_t*>(&p1),
                   *reinterpret_cast<uint32_t*>(&p2), *reinterpret_cast<uint32_t*>(&p3));
}

// ---------------- aggregation, layer 2 ----------------
__global__ __launch_bounds__(256) void k_agg_l2(
    const __half* __restrict__ zh, const float* __restrict__ inv,
    const float* __restrict__ bias,
    const float* __restrict__ r2m, float* __restrict__ logits, int n)
{
    __shared__ float sout[8][240];
    int wInB = threadIdx.x >> 5;
    int gw = blockIdx.x * 8 + wInB;
    int lane = threadIdx.x & 31;
    bool act = (lane < 30);
    if (gw < n) {
        int beg = g_rowstart[gw], end = g_rowstart[gw + 1];
        int h = act ? (lane / 5) : 0;
        const __half* wp = g_wp + (size_t)h * ECAP;
        int c0 = lane * 8;
        float2 accf[4] = {{0.f,0.f},{0.f,0.f},{0.f,0.f},{0.f,0.f}};
        int i = beg;
        for (; i < end && (i & 3); ++i) {
            int s0 = __ldg(&g_srcs[i]);
            if (act) {
                uint4 q0 = __ldg(reinterpret_cast<const uint4*>(zh + (size_t)s0 * 240 + c0));
                one_acc(accf, q0, __half2half2(__ldg(&wp[i])));
            }
        }
        #pragma unroll 1
        for (; i + 4 <= end; i += 4) {
            int4 s4 = __ldg(reinterpret_cast<const int4*>(&g_srcs[i]));
            if (act) {
                uint2 w4 = __ldg(reinterpret_cast<const uint2*>(&wp[i]));
                uint4 q0 = __ldg(reinterpret_cast<const uint4*>(zh + (size_t)s4.x * 240 + c0));
                uint4 q1 = __ldg(reinterpret_cast<const uint4*>(zh + (size_t)s4.y * 240 + c0));
                uint4 q2 = __ldg(reinterpret_cast<const uint4*>(zh + (size_t)s4.z * 240 + c0));
                uint4 q3 = __ldg(reinterpret_cast<const uint4*>(zh + (size_t)s4.w * 240 + c0));
                __half2 wa = *reinterpret_cast<__half2*>(&w4.x);
                __half2 wb = *reinterpret_cast<__half2*>(&w4.y);
                quad_acc(accf, q0, q1, q2, q3,
                         __half2half2(__low2half(wa)), __half2half2(__high2half(wa)),
                         __half2half2(__low2half(wb)), __half2half2(__high2half(wb)));
            }
        }
        for (; i < end; ++i) {
            int s0 = __ldg(&g_srcs[i]);
            if (act) {
                uint4 q0 = __ldg(reinterpret_cast<const uint4*>(zh + (size_t)s0 * 240 + c0));
                one_acc(accf, q0, __half2half2(__ldg(&wp[i])));
            }
        }
        if (act) {
            float invv = __ldg(&inv[gw * 6 + h]);
            const float4* bp = reinterpret_cast<const float4*>(bias + c0);
            float4 b0 = __ldg(bp), b1 = __ldg(bp + 1);
            sout[wInB][c0 + 0] = fmaf(accf[0].x, invv, b0.x);
            sout[wInB][c0 + 1] = fmaf(accf[0].y, invv, b0.y);
            sout[wInB][c0 + 2] = fmaf(accf[1].x, invv, b0.z);
            sout[wInB][c0 + 3] = fmaf(accf[1].y, invv, b0.w);
            sout[wInB][c0 + 4] = fmaf(accf[2].x, invv, b1.x);
            sout[wInB][c0 + 5] = fmaf(accf[2].y, invv, b1.y);
            sout[wInB][c0 + 6] = fmaf(accf[3].x, invv, b1.z);
            sout[wInB][c0 + 7] = fmaf(accf[3].y, invv, b1.w);
        }
    }
    __syncwarp();
    if (gw < n) {
        for (int d = lane; d < 40; d += 32) {
            float s_ = 0.f;
            #pragma unroll
            for (int hh = 0; hh < 6; ++hh) s_ += sout[wInB][hh * 40 + d];
            logits[(size_t)gw * 40 + d] = s_ * (1.0f / 6.0f) + __ldg(&r2m[(size_t)gw * 40 + d]);
        }
    }
}

// ---------------- host ----------------
extern "C" void kernel_launch(void* const* d_in, const int* in_sizes, int n_in,
                              void* d_out, int out_size)
{
    const float* feat  = (const float*)d_in[0];
    const int*   src   = (const int*)d_in[1];
    const int*   dst   = (const int*)d_in[2];
    const float* W0    = (const float*)d_in[3];
    const float* al0   = (const float*)d_in[4];
    const float* ar0   = (const float*)d_in[5];
    const float* b0    = (const float*)d_in[6];
    const float* W1    = (const float*)d_in[7];
    const float* al1   = (const float*)d_in[8];
    const float* ar1   = (const float*)d_in[9];
    const float* b1    = (const float*)d_in[10];
    const float* W2    = (const float*)d_in[11];
    const float* al2   = (const float*)d_in[12];
    const float* ar2   = (const float*)d_in[13];
    const float* b2    = (const float*)d_in[14];
    const float* resW2 = (const float*)d_in[15];

    const int n = NNODES;
    const int E = in_sizes[1];

    float* logits = (float*)d_out;
    float* h1     = (float*)d_out + n * 40;

    float *pr2, *pelA, *perA, *pelB, *perB, *pinv;
    __half *pzh, *pAh;
    int* pdeg;
    cudaGetSymbolAddress((void**)&pzh,  g_zh);
    cudaGetSymbolAddress((void**)&pr2,  g_r2);
    cudaGetSymbolAddress((void**)&pelA, g_elA);
    cudaGetSymbolAddress((void**)&perA, g_erA);
    cudaGetSymbolAddress((void**)&pelB, g_elB);
    cudaGetSymbolAddress((void**)&perB, g_erB);
    cudaGetSymbolAddress((void**)&pinv, g_inv);
    cudaGetSymbolAddress((void**)&pAh,  g_Ah);
    cudaGetSymbolAddress((void**)&pdeg, g_deg);

    cudaFuncSetAttribute(k_gemm0, cudaFuncAttributeMaxDynamicSharedMemorySize, GEMM_SMEM128);
    cudaFuncSetAttribute(k_gemm1, cudaFuncAttributeMaxDynamicSharedMemorySize, GEMM_SMEM128);
    cudaFuncSetAttribute(k_gemm2, cudaFuncAttributeMaxDynamicSharedMemorySize, GEMM_SMEM128);

    const int nGemm = ((n + 63) / 64) * 2;
    const int nGemmM = (n + 63) / 64;
    const int histBlocks = (E + 255) / 256;
    const int scatBlocks = (E + 127) / 128;
    const int zeroBlocks = (n * 6 + 255) / 256;
    const int aggBlocks  = (n + 7) / 8;

    cudaMemsetAsync(pdeg, 0, n * sizeof(int));
    k_prep0<<<SPLITA_BLOCKS + 256 + histBlocks, 256>>>(feat, W0, dst, E);
    k_scan<<<1, 1024>>>(n, E);
    // Layer 0
    k_gemm0<<<nGemm + scatBlocks, 128, GEMM_SMEM128>>>(pAh, pzh, al0, ar0, pelA, perA,
                                                       n, nGemm, src, dst, E);
    k_wgt<4><<<aggBlocks, 256>>>(pelA, perA, pinv, n);
    k_agg256<false><<<aggBlocks + 256, 256>>>(
        pzh, pinv, b0, nullptr, pAh, n, aggBlocks,
        W1, 256, nullptr, nullptr, nullptr, 0);
    // Layer 1
    k_gemm1<<<nGemm, 128, GEMM_SMEM128>>>(pAh, pzh, al1, ar1, pelB, perB, n);
    k_wgt<4><<<aggBlocks, 256>>>(pelB, perB, pinv, n);
    k_agg256<true><<<aggBlocks + 256 + 64 + zeroBlocks, 256>>>(
        pzh, pinv, b1, h1, pAh, n, aggBlocks,
        W2, 240, resW2, pelA, perA, n * 6);
    // Layer 2
    k_gemm2<<<nGemm + nGemmM, 128, GEMM_SMEM128>>>(pAh, pzh, pr2, al2, ar2, pelA, perA,
                                                   n, nGemm);
    k_wgt<6><<<aggBlocks, 256>>>(pelA, perA, pinv, n);
    k_agg_l2<<<aggBlocks, 256>>>(pzh, pinv, b2, pr2, logits, n);
}

// round 16
// speedup vs baseline: 1.0513x; 1.0513x over previous
#include <cuda_runtime.h>
#include <cuda_fp16.h>
#include <math.h>
#include <cstdint>

// ---------------- problem constants ----------------
#define NNODES 50000
#define ECAP   1000000
#define SPLITA_BLOCKS 12500
#define WSCALE 3.4657359028f  // ln(32): w' = exp(e - ln32); cancels in softmax

// ---------------- device scratch ----------------
__device__ __align__(16) __half g_zh[NNODES * 256];
__device__ float g_r2[NNODES * 40];
__device__ float g_elA[NNODES * 6];
__device__ float g_erA[NNODES * 6];
__device__ float g_elB[NNODES * 6];
__device__ float g_erB[NNODES * 6];
__device__ int   g_deg[NNODES];
__device__ int   g_rowstart[NNODES + 1];
__device__ int   g_cursor[NNODES];
__device__ int   g_srcs[ECAP];
__device__ __align__(16) __half g_Ah[NNODES * 256];
__device__ __align__(16) __half g_Bh[256 * 256];
__device__ __align__(16) __half g_Bh2[64 * 256];

// ================= PTX helpers =================
__device__ __forceinline__ uint32_t smem_u32(const void* p) {
    uint32_t a;
    asm("{ .reg .u64 t; cvta.to.shared.u64 t, %1; cvt.u32.u64 %0, t; }" : "=r"(a) : "l"(p));
    return a;
}
__device__ __forceinline__ void cp16(uint32_t dst, const void* src, uint32_t srcsize) {
    asm volatile("cp.async.cg.shared.global [%0], [%1], 16, %2;"
                 :: "r"(dst), "l"(src), "r"(srcsize));
}
#define CP_COMMIT() asm volatile("cp.async.commit_group;" ::: "memory")
#define CP_WAIT(n)  asm volatile("cp.async.wait_group %0;" :: "n"(n) : "memory")
#define LDSM_X4(r0, r1, r2, r3, addr) \
    asm volatile("ldmatrix.sync.aligned.m8n8.x4.shared.b16 {%0,%1,%2,%3}, [%4];" \
        : "=r"(r0), "=r"(r1), "=r"(r2), "=r"(r3) : "r"(addr))
#define MMA_F16(acc, a, b) \
    asm volatile("mma.sync.aligned.m16n8k16.row.col.f32.f16.f16.f32 " \
        "{%0,%1,%2,%3}, {%4,%5,%6,%7}, {%8,%9}, {%0,%1,%2,%3};" \
        : "+f"((acc)[0]), "+f"((acc)[1]), "+f"((acc)[2]), "+f"((acc)[3]) \
        : "r"((a)[0]), "r"((a)[1]), "r"((a)[2]), "r"((a)[3]), "r"((b)[0]), "r"((b)[1]))

// ---------------- helpers ----------------
__device__ __forceinline__ void convBt_elem(const float* __restrict__ B,
                                            __half* __restrict__ out, int t, int Nn) {
    int nrow = t >> 8, k = t & 255;
    float x = (nrow < Nn) ? B[(size_t)k * Nn + nrow] : 0.f;
    out[t] = __float2half_rn(x);
}
__device__ __forceinline__ void resmean_elem(const float* __restrict__ resW2, int t) {
    int d = t >> 8, k = t & 255;
    float x = 0.f;
    if (d < 40) {
        float s_ = 0.f;
        #pragma unroll
        for (int h = 0; h < 6; ++h) s_ += resW2[(size_t)k * 240 + h * 40 + d];
        x = s_ * (1.0f / 6.0f);
    }
    g_Bh2[t] = __float2half_rn(x);
}

// ---------------- prep0 ----------------
__global__ void k_prep0(const float* __restrict__ feat, const float* __restrict__ W0,
                        const int* __restrict__ dst, int E) {
    int bx = blockIdx.x;
    if (bx < SPLITA_BLOCKS) {
        int i = bx * 256 + threadIdx.x;
        float4 v = reinterpret_cast<const float4*>(feat)[i];
        __half2 p0 = __floats2half2_rn(v.x, v.y);
        __half2 p1 = __floats2half2_rn(v.z, v.w);
        reinterpret_cast<uint2*>(g_Ah)[i] =
            make_uint2(*reinterpret_cast<uint32_t*>(&p0), *reinterpret_cast<uint32_t*>(&p1));
    } else if (bx < SPLITA_BLOCKS + 256) {
        int t = (bx - SPLITA_BLOCKS) * 256 + threadIdx.x;
        convBt_elem(W0, g_Bh, t, 256);
    } else {
        int e = (bx - SPLITA_BLOCKS - 256) * 256 + threadIdx.x;
        if (e < E) atomicAdd(&g_deg[dst[e]], 1);
    }
}

// ---------------- scan ----------------
__global__ void k_scan(int n, int E) {
    __shared__ int wsum[32];
    __shared__ int carry;
    int lane = threadIdx.x & 31, w = threadIdx.x >> 5;
    if (threadIdx.x == 0) carry = 0;
    __syncthreads();
    for (int base = 0; base < n; base += 1024) {
        int i = base + threadIdx.x;
        int v = (i < n) ? g_deg[i] : 0;
        int x = v;
        #pragma unroll
        for (int off = 1; off < 32; off <<= 1) {
            int t = __shfl_up_sync(0xffffffffu, x, off);
            if (lane >= off) x += t;
        }
        if (lane == 31) wsum[w] = x;
        __syncthreads();
        if (w == 0) {
            int y = wsum[lane];
            #pragma unroll
            for (int off = 1; off < 32; off <<= 1) {
                int t = __shfl_up_sync(0xffffffffu, y, off);
                if (lane >= off) y += t;
            }
            wsum[lane] = y;
        }
        __syncthreads();
        int incl = x + (w ? wsum[w - 1] : 0) + carry;
        int excl = incl - v;
        if (i < n) { g_rowstart[i] = excl; g_cursor[i] = excl; }
        __syncthreads();
        if (threadIdx.x == 1023) carry = incl;
        __syncthreads();
    }
    if (threadIdx.x == 0) g_rowstart[n] = E;
}

// ---------------- GEMM body (fp16 mma.sync, BM=64, 128 threads, 2-stage) ----------------
template <int BN>
__device__ __forceinline__ void gemm_load_stage(
    uint32_t sb, const __half* __restrict__ Ah, const __half* __restrict__ Bh,
    int m0, int n0, int M, int kb, int tid)
{
    #pragma unroll
    for (int it = 0; it < 4; ++it) {
        int idx = tid + it * 128;
        int row = idx >> 3, ch = idx & 7;
        uint32_t dst = sb + row * 128 + (((uint32_t)(ch ^ (row & 7))) << 4);
        const __half* src = Ah + (size_t)(m0 + row) * 256 + kb * 64 + ch * 8;
        cp16(dst, src, (m0 + row) < M ? 16u : 0u);
    }
    #pragma unroll
    for (int it = 0; it < (BN * 8) / 128; ++it) {
        int idx = tid + it * 128;
        int row = idx >> 3, ch = idx & 7;
        uint32_t dst = sb + 8192 + row * 128 + (((uint32_t)(ch ^ (row & 7))) << 4);
        const __half* src = Bh + (size_t)(n0 + row) * 256 + kb * 64 + ch * 8;
        cp16(dst, src, 16u);
    }
}

template <int MODE, int BN>
__device__ __forceinline__ void gemm_body(
    const __half* __restrict__ Ah, const __half* __restrict__ Bh,
    __half* __restrict__ Ch, float* __restrict__ Cf,
    const float* __restrict__ al, const float* __restrict__ ar,
    float* __restrict__ el, float* __restrict__ er,
    int M, int Nn, int H, int D, int m0, int n0)
{
    constexpr int NT = BN / 16;
    constexpr uint32_t STAGE = 8192u + (uint32_t)BN * 128u;
    extern __shared__ char smem[];
    const uint32_t sbase = smem_u32(smem);
    const int tid = threadIdx.x, wid = tid >> 5, lane = tid & 31;
    const int warp_m = wid & 1, warp_n = wid >> 1;

    float acc[2][NT][4];
    #pragma unroll
    for (int mt = 0; mt < 2; ++mt)
        #pragma unroll
        for (int nt = 0; nt < NT; ++nt)
            #pragma unroll
            for (int q = 0; q < 4; ++q) acc[mt][nt][q] = 0.f;

    const int rowA = warp_m * 32 + (lane & 15);
    const int rowB = warp_n * (BN / 2) + (lane & 7) + ((lane >> 4) << 3);
    const uint32_t rowAswz = (uint32_t)(rowA & 7);
    const uint32_t rowBswz = (uint32_t)(rowB & 7);
    const int halfA = lane >> 4;
    const int halfB = (lane >> 3) & 1;

    gemm_load_stage<BN>(sbase, Ah, Bh, m0, n0, M, 0, tid);
    CP_COMMIT();
    gemm_load_stage<BN>(sbase + STAGE, Ah, Bh, m0, n0, M, 1, tid);
    CP_COMMIT();

    #pragma unroll 1
    for (int kb = 0; kb < 4; ++kb) {
        if (kb < 3) { CP_WAIT(1); } else { CP_WAIT(0); }
        __syncthreads();
        const uint32_t sb = sbase + (kb & 1) * STAGE;
        #pragma unroll
        for (int s = 0; s < 4; ++s) {
            uint32_t a[2][4];
            uint32_t b[NT][2];
            const uint32_t offA = (((uint32_t)(s * 2 + halfA) ^ rowAswz) << 4);
            const uint32_t offB = (((uint32_t)(s * 2 + halfB) ^ rowBswz) << 4);
            #pragma unroll
            for (int mt = 0; mt < 2; ++mt) {
                uint32_t addr = sb + (uint32_t)(rowA + mt * 16) * 128 + offA;
                LDSM_X4(a[mt][0], a[mt][1], a[mt][2], a[mt][3], addr);
            }
            #pragma unroll
            for (int ntp = 0; ntp < NT / 2; ++ntp) {
                uint32_t addr = sb + 8192 + (uint32_t)(rowB + ntp * 16) * 128 + offB;
                LDSM_X4(b[2 * ntp][0], b[2 * ntp][1], b[2 * ntp + 1][0], b[2 * ntp + 1][1], addr);
            }
            #pragma unroll
            for (int mt = 0; mt < 2; ++mt)
                #pragma unroll
                for (int nt = 0; nt < NT; ++nt)
                    MMA_F16(acc[mt][nt], a[mt], b[nt]);
        }
        __syncthreads();
        if (kb < 2) {
            gemm_load_stage<BN>(sbase + (kb & 1) * STAGE, Ah, Bh, m0, n0, M, kb + 2, tid);
            CP_COMMIT();
        }
    }

    #pragma unroll
    for (int mt = 0; mt < 2; ++mt) {
        int row = m0 + warp_m * 32 + mt * 16 + (lane >> 2);
        #pragma unroll
        for (int nt = 0; nt < NT; ++nt) {
            int col = n0 + warp_n * (BN / 2) + nt * 8 + (lane & 3) * 2;
            if (col < Nn) {
                if (MODE != 0) {
                    if (row < M)
                        *reinterpret_cast<__half2*>(Ch + (size_t)row * Nn + col) =
                            __floats2half2_rn(acc[mt][nt][0], acc[mt][nt][1]);
                    if (row + 8 < M)
                        *reinterpret_cast<__half2*>(Ch + (size_t)(row + 8) * Nn + col) =
                            __floats2half2_rn(acc[mt][nt][2], acc[mt][nt][3]);
                } else {
                    if (row < M)
                        *reinterpret_cast<float2*>(Cf + (size_t)row * Nn + col) =
                            make_float2(acc[mt][nt][0], acc[mt][nt][1]);
                    if (row + 8 < M)
                        *reinterpret_cast<float2*>(Cf + (size_t)(row + 8) * Nn + col) =
                            make_float2(acc[mt][nt][2], acc[mt][nt][3]);
                }
            }
        }
    }

    if (MODE == 1) {
        const int h = (n0 + warp_n * 64) >> 6;
        float sl[2][2] = {}, sr[2][2] = {};
        #pragma unroll
        for (int nt = 0; nt < NT; ++nt) {
            int dloc = nt * 8 + (lane & 3) * 2;
            float2 av = __ldg(reinterpret_cast<const float2*>(al + h * 64 + dloc));
            float2 rv = __ldg(reinterpret_cast<const float2*>(ar + h * 64 + dloc));
            #pragma unroll
            for (int mt = 0; mt < 2; ++mt) {
                sl[mt][0] += acc[mt][nt][0] * av.x + acc[mt][nt][1] * av.y;
                sr[mt][0] += acc[mt][nt][0] * rv.x + acc[mt][nt][1] * rv.y;
                sl[mt][1] += acc[mt][nt][2] * av.x + acc[mt][nt][3] * av.y;
                sr[mt][1] += acc[mt][nt][2] * rv.x + acc[mt][nt][3] * rv.y;
            }
        }
        #pragma unroll
        for (int mt = 0; mt < 2; ++mt)
            #pragma unroll
            for (int rh = 0; rh < 2; ++rh) {
                float vl = sl[mt][rh], vr = sr[mt][rh];
                vl += __shfl_xor_sync(0xffffffffu, vl, 1);
                vl += __shfl_xor_sync(0xffffffffu, vl, 2);
                vr += __shfl_xor_sync(0xffffffffu, vr, 1);
                vr += __shfl_xor_sync(0xffffffffu, vr, 2);
                sl[mt][rh] = vl; sr[mt][rh] = vr;
            }
        if ((lane & 3) == 0) {
            #pragma unroll
            for (int mt = 0; mt < 2; ++mt)
                #pragma unroll
                for (int rh = 0; rh < 2; ++rh) {
                    int row = m0 + warp_m * 32 + mt * 16 + (lane >> 2) + rh * 8;
                    if (row < M) {
                        el[(size_t)row * H + h] = sl[mt][rh];
                        er[(size_t)row * H + h] = sr[mt][rh];
                    }
                }
        }
    } else if (MODE == 2) {
        const int colbase = n0 + warp_n * (BN / 2);
        if (colbase < Nn) {
            const int h0 = colbase / D;
            const int colend = (colbase + BN / 2 < Nn) ? (colbase + BN / 2) : Nn;
            const int hmax = (colend - 1) / D;
            float sl[2][2][3] = {}, sr[2][2][3] = {};
            #pragma unroll
            for (int nt = 0; nt < NT; ++nt) {
                int colg = colbase + nt * 8;
                if (colg < Nn) {
                    int h = colg / D;
                    int slot = h - h0;
                    if (slot > 2) slot = 2;
                    int d = colg - h * D + (lane & 3) * 2;
                    float2 av = __ldg(reinterpret_cast<const float2*>(al + h * D + d));
                    float2 rv = __ldg(reinterpret_cast<const float2*>(ar + h * D + d));
                    #pragma unroll
                    for (int mt = 0; mt < 2; ++mt) {
                        sl[mt][0][slot] += acc[mt][nt][0] * av.x + acc[mt][nt][1] * av.y;
                        sr[mt][0][slot] += acc[mt][nt][0] * rv.x + acc[mt][nt][1] * rv.y;
                        sl[mt][1][slot] += acc[mt][nt][2] * av.x + acc[mt][nt][3] * av.y;
                        sr[mt][1][slot] += acc[mt][nt][2] * rv.x + acc[mt][nt][3] * rv.y;
                    }
                }
            }
            #pragma unroll
            for (int mt = 0; mt < 2; ++mt)
                #pragma unroll
                for (int rh = 0; rh < 2; ++rh)
                    #pragma unroll
                    for (int sx = 0; sx < 3; ++sx) {
                        float vl = sl[mt][rh][sx], vr = sr[mt][rh][sx];
                        vl += __shfl_xor_sync(0xffffffffu, vl, 1);
                        vl += __shfl_xor_sync(0xffffffffu, vl, 2);
                        vr += __shfl_xor_sync(0xffffffffu, vr, 1);
                        vr += __shfl_xor_sync(0xffffffffu, vr, 2);
                        sl[mt][rh][sx] = vl; sr[mt][rh][sx] = vr;
                    }
            if ((lane & 3) == 0) {
                int nslots = hmax - h0 + 1;
                if (nslots > 3) nslots = 3;
                #pragma unroll
                for (int mt = 0; mt < 2; ++mt)
                    #pragma unroll
                    for (int rh = 0; rh < 2; ++rh) {
                        int row = m0 + warp_m * 32 + mt * 16 + (lane >> 2) + rh * 8;
                        if (row < M) {
                            for (int sx = 0; sx < nslots; ++sx) {
                                atomicAdd(&el[(size_t)row * H + h0 + sx], sl[mt][rh][sx]);
                                atomicAdd(&er[(size_t)row * H + h0 + sx], sr[mt][rh][sx]);
                            }
                        }
                    }
            }
        }
    }
}

#define GEMM_SMEM128 (2 * (8192 + 128 * 128))

// ---------------- GEMM launches ----------------
__global__ __launch_bounds__(128, 4) void k_gemm0(
    const __half* __restrict__ Ah, __half* __restrict__ Ch,
    const float* __restrict__ al, const float* __restrict__ ar,
    float* __restrict__ el, float* __restrict__ er, int M, int nGemm,
    const int* __restrict__ src, const int* __restrict__ dst, int E)
{
    int bx = blockIdx.x;
    if (bx < nGemm) {
        gemm_body<1, 128>(Ah, g_Bh, Ch, nullptr, al, ar, el, er,
                          M, 256, 4, 64, (bx >> 1) * 64, (bx & 1) * 128);
    } else {
        int e = (bx - nGemm) * 128 + threadIdx.x;
        if (e < E) {
            int p = atomicAdd(&g_cursor[dst[e]], 1);
            g_srcs[p] = src[e];
        }
    }
}

__global__ __launch_bounds__(128, 4) void k_gemm1(
    const __half* __restrict__ Ah, __half* __restrict__ Ch,
    const float* __restrict__ al, const float* __restrict__ ar,
    float* __restrict__ el, float* __restrict__ er, int M)
{
    int bx = blockIdx.x;
    gemm_body<1, 128>(Ah, g_Bh, Ch, nullptr, al, ar, el, er,
                      M, 256, 4, 64, (bx >> 1) * 64, (bx & 1) * 128);
}

__global__ __launch_bounds__(128, 4) void k_gemm2(
    const __half* __restrict__ Ah, __half* __restrict__ Ch, float* __restrict__ Cf,
    const float* __restrict__ al, const float* __restrict__ ar,
    float* __restrict__ el, float* __restrict__ er, int M, int nGemm)
{
    int bx = blockIdx.x;
    if (bx < nGemm) {
        gemm_body<2, 128>(Ah, g_Bh, Ch, nullptr, al, ar, el, er,
                          M, 240, 6, 40, (bx >> 1) * 64, (bx & 1) * 128);
    } else {
        gemm_body<0, 64>(Ah, g_Bh2, nullptr, Cf, nullptr, nullptr, nullptr, nullptr,
                         M, 40, 1, 64, (bx - nGemm) * 64, 0);
    }
}

// ---------------- fp16 quad-tree accumulate ----------------
__device__ __forceinline__ void quad_acc(
    float2* accf, const uint4& q0, const uint4& q1, const uint4& q2, const uint4& q3,
    __half2 w0, __half2 w1, __half2 w2, __half2 w3)
{
    const __half2* z0 = reinterpret_cast<const __half2*>(&q0);
    const __half2* z1 = reinterpret_cast<const __half2*>(&q1);
    const __half2* z2 = reinterpret_cast<const __half2*>(&q2);
    const __half2* z3 = reinterpret_cast<const __half2*>(&q3);
    #pragma unroll
    for (int j = 0; j < 4; ++j) {
        __half2 t = __hadd2(__hadd2(__hmul2(w0, z0[j]), __hmul2(w1, z1[j])),
                            __hadd2(__hmul2(w2, z2[j]), __hmul2(w3, z3[j])));
        float2 tf = __half22float2(t);
        accf[j].x += tf.x;
        accf[j].y += tf.y;
    }
}
__device__ __forceinline__ void one_acc(float2* accf, const uint4& q, __half2 w)
{
    const __half2* z = reinterpret_cast<const __half2*>(&q);
    #pragma unroll
    for (int j = 0; j < 4; ++j) {
        float2 tf = __half22float2(__hmul2(w, z[j]));
        accf[j].x += tf.x;
        accf[j].y += tf.y;
    }
}

// ---------------- aggregation, layers 0/1 (attention spread over 16 lanes) ----------------
template <bool RES>
__global__ __launch_bounds__(256) void k_agg256(
    const __half* __restrict__ zh, const float* __restrict__ el,
    const float* __restrict__ er, const float* __restrict__ bias,
    float* __restrict__ out, __half* __restrict__ oah, int n, int nAgg,
    const float* __restrict__ Wnext, int convN,
    const float* __restrict__ resW2,
    float* __restrict__ zel, float* __restrict__ zer, int n6)
{
    int bx = blockIdx.x;
    if (bx >= nAgg) {
        int t = bx - nAgg;
        if (t < 256) {
            convBt_elem(Wnext, g_Bh, t * 256 + threadIdx.x, convN);
        } else if (resW2 != nullptr && t < 320) {
            resmean_elem(resW2, (t - 256) * 256 + threadIdx.x);
        } else if (zel != nullptr) {
            int zoff = (resW2 != nullptr) ? 320 : 256;
            int i = (t - zoff) * 256 + threadIdx.x;
            if (i < n6) { zel[i] = 0.f; zer[i] = 0.f; }
        }
        return;
    }
    int gw = (bx * 256 + threadIdx.x) >> 5;
    if (gw >= n) return;
    int lane = threadIdx.x & 31;
    int beg = g_rowstart[gw], end = g_rowstart[gw + 1];
    // attention lanes: lane<16 -> (head lh = lane>>2, edge le = lane&3)
    const int le = lane & 3, lh = lane >> 2;
    const bool wact = lane < 16;
    const float erh = wact ? __ldg(&er[gw * 4 + lh]) : 0.f;
    const int hsrc = (lane >> 3) * 4;   // shuffle source base for this lane's head
    int c0 = lane * 8;
    float2 accf[4] = {{0.f,0.f},{0.f,0.f},{0.f,0.f},{0.f,0.f}};
    float denom = 0.f;
    int i = beg;
    #pragma unroll 1
    for (; i + 4 <= end; i += 4) {
        int s0 = __ldg(&g_srcs[i]);
        int s1 = __ldg(&g_srcs[i + 1]);
        int s2 = __ldg(&g_srcs[i + 2]);
        int s3 = __ldg(&g_srcs[i + 3]);
        uint4 q0 = __ldg(reinterpret_cast<const uint4*>(zh + (size_t)s0 * 256 + c0));
        uint4 q1 = __ldg(reinterpret_cast<const uint4*>(zh + (size_t)s1 * 256 + c0));
        uint4 q2 = __ldg(reinterpret_cast<const uint4*>(zh + (size_t)s2 * 256 + c0));
        uint4 q3 = __ldg(reinterpret_cast<const uint4*>(zh + (size_t)s3 * 256 + c0));
        int se = (le == 0) ? s0 : (le == 1) ? s1 : (le == 2) ? s2 : s3;
        float w = 0.f;
        if (wact) {
            float e = __ldg(&el[se * 4 + lh]) + erh;
            e = (e > 0.f) ? e : 0.2f * e;
            w = __expf(e - WSCALE);
            denom += w;
        }
        __half2 wh0 = __float2half2_rn(__shfl_sync(0xffffffffu, w, hsrc + 0));
        __half2 wh1 = __float2half2_rn(__shfl_sync(0xffffffffu, w, hsrc + 1));
        __half2 wh2 = __float2half2_rn(__shfl_sync(0xffffffffu, w, hsrc + 2));
        __half2 wh3 = __float2half2_rn(__shfl_sync(0xffffffffu, w, hsrc + 3));
        quad_acc(accf, q0, q1, q2, q3, wh0, wh1, wh2, wh3);
    }
    #pragma unroll 1
    for (; i < end; ++i) {
        int s0 = __ldg(&g_srcs[i]);
        uint4 q0 = __ldg(reinterpret_cast<const uint4*>(zh + (size_t)s0 * 256 + c0));
        float w = 0.f;
        if (wact && le == 0) {
            float e = __ldg(&el[s0 * 4 + lh]) + erh;
            e = (e > 0.f) ? e : 0.2f * e;
            w = __expf(e - WSCALE);
            denom += w;
        }
        __half2 wh0 = __float2half2_rn(__shfl_sync(0xffffffffu, w, hsrc));
        one_acc(accf, q0, wh0);
    }
    // reduce denom over edges (le bits 0..1), then broadcast to head groups
    denom += __shfl_xor_sync(0xffffffffu, denom, 1);
    denom += __shfl_xor_sync(0xffffffffu, denom, 2);
    float dh = __shfl_sync(0xffffffffu, denom, hsrc);
    float invv = 1.f / dh;
    const float4* bp = reinterpret_cast<const float4*>(bias + c0);
    float4 b0 = __ldg(bp), b1 = __ldg(bp + 1);
    float v[8];
    v[0] = fmaf(accf[0].x, invv, b0.x); v[1] = fmaf(accf[0].y, invv, b0.y);
    v[2] = fmaf(accf[1].x, invv, b0.z); v[3] = fmaf(accf[1].y, invv, b0.w);
    v[4] = fmaf(accf[2].x, invv, b1.x); v[5] = fmaf(accf[2].y, invv, b1.y);
    v[6] = fmaf(accf[3].x, invv, b1.z); v[7] = fmaf(accf[3].y, invv, b1.w);
    if (RES) {
        uint4 rq = *reinterpret_cast<const uint4*>(oah + (size_t)gw * 256 + c0);
        float2 r0 = __half22float2(*reinterpret_cast<__half2*>(&rq.x));
        float2 r1 = __half22float2(*reinterpret_cast<__half2*>(&rq.y));
        float2 r2 = __half22float2(*reinterpret_cast<__half2*>(&rq.z));
        float2 r3 = __half22float2(*reinterpret_cast<__half2*>(&rq.w));
        v[0] += r0.x; v[1] += r0.y; v[2] += r1.x; v[3] += r1.y;
        v[4] += r2.x; v[5] += r2.y; v[6] += r3.x; v[7] += r3.y;
    }
    #pragma unroll
    for (int j = 0; j < 8; ++j) v[j] = (v[j] > 0.f) ? v[j] : expm1f(v[j]);
    if (out != nullptr) {
        float4* op = reinterpret_cast<float4*>(out + (size_t)gw * 256 + c0);
        op[0] = make_float4(v[0], v[1], v[2], v[3]);
        op[1] = make_float4(v[4], v[5], v[6], v[7]);
    }
    __half2 p0 = __floats2half2_rn(v[0], v[1]);
    __half2 p1 = __floats2half2_rn(v[2], v[3]);
    __half2 p2 = __floats2half2_rn(v[4], v[5]);
    __half2 p3 = __floats2half2_rn(v[6], v[7]);
    *reinterpret_cast<uint4*>(oah + (size_t)gw * 256 + c0) =
        make_uint4(*reinterpret_cast<uint32_t*>(&p0), *reinterpret_cast<uint32_t*>(&p1),
                   *reinterpret_cast<uint32_t*>(&p2), *reinterpret_cast<uint32_t*>(&p3));
}

// ---------------- aggregation, layer 2 (attention spread over 24 lanes) ----------------
__global__ __launch_bounds__(256) void k_agg_l2(
    const __half* __restrict__ zh, const float* __restrict__ el,
    const float* __restrict__ er, const float* __restrict__ bias,
    const float* __restrict__ r2m, float* __restrict__ logits, int n)
{
    __shared__ float sout[8][240];
    int wInB = threadIdx.x >> 5;
    int gw = blockIdx.x * 8 + wInB;
    int lane = threadIdx.x & 31;
    bool act = (lane < 30);
    if (gw < n) {
        int beg = g_rowstart[gw], end = g_rowstart[gw + 1];
        const int le = lane & 3, lh = lane >> 2;     // lh 0..7
        const bool wact = lane < 24;                  // lh 0..5
        const float erh = wact ? __ldg(&er[gw * 6 + lh]) : 0.f;
        const int h = act ? (lane / 5) : 0;
        const int hsrc = h * 4;
        int c0 = lane * 8;
        float2 accf[4] = {{0.f,0.f},{0.f,0.f},{0.f,0.f},{0.f,0.f}};
        float denom = 0.f;
        int i = beg;
        #pragma unroll 1
        for (; i + 4 <= end; i += 4) {
            int s0 = __ldg(&g_srcs[i]);
            int s1 = __ldg(&g_srcs[i + 1]);
            int s2 = __ldg(&g_srcs[i + 2]);
            int s3 = __ldg(&g_srcs[i + 3]);
            uint4 q0 = make_uint4(0, 0, 0, 0), q1 = q0, q2 = q0, q3 = q0;
            if (act) {
                q0 = __ldg(reinterpret_cast<const uint4*>(zh + (size_t)s0 * 240 + c0));
                q1 = __ldg(reinterpret_cast<const uint4*>(zh + (size_t)s1 * 240 + c0));
                q2 = __ldg(reinterpret_cast<const uint4*>(zh + (size_t)s2 * 240 + c0));
                q3 = __ldg(reinterpret_cast<const uint4*>(zh + (size_t)s3 * 240 + c0));
            }
            int se = (le == 0) ? s0 : (le == 1) ? s1 : (le == 2) ? s2 : s3;
            float w = 0.f;
            if (wact) {
                float e = __ldg(&el[se * 6 + lh]) + erh;
                e = (e > 0.f) ? e : 0.2f * e;
                w = __expf(e - WSCALE);
                denom += w;
            }
            __half2 wh0 = __float2half2_rn(__shfl_sync(0xffffffffu, w, hsrc + 0));
            __half2 wh1 = __float2half2_rn(__shfl_sync(0xffffffffu, w, hsrc + 1));
            __half2 wh2 = __float2half2_rn(__shfl_sync(0xffffffffu, w, hsrc + 2));
            __half2 wh3 = __float2half2_rn(__shfl_sync(0xffffffffu, w, hsrc + 3));
            if (act) quad_acc(accf, q0, q1, q2, q3, wh0, wh1, wh2, wh3);
        }
        #pragma unroll 1
        for (; i < end; ++i) {
            int s0 = __ldg(&g_srcs[i]);
            uint4 q0 = make_uint4(0, 0, 0, 0);
            if (act) q0 = __ldg(reinterpret_cast<const uint4*>(zh + (size_t)s0 * 240 + c0));
            float w = 0.f;
            if (wact && le == 0) {
                float e = __ldg(&el[s0 * 6 + lh]) + erh;
                e = (e > 0.f) ? e : 0.2f * e;
                w = __expf(e - WSCALE);
                denom += w;
            }
            __half2 wh0 = __float2half2_rn(__shfl_sync(0xffffffffu, w, hsrc));
            if (act) one_acc(accf, q0, wh0);
        }
        denom += __shfl_xor_sync(0xffffffffu, denom, 1);
        denom += __shfl_xor_sync(0xffffffffu, denom, 2);
        float dh = __shfl_sync(0xffffffffu, denom, hsrc);
        if (act) {
            float invv = 1.f / dh;
            const float4* bp = reinterpret_cast<const float4*>(bias + c0);
            float4 b0 = __ldg(bp), b1 = __ldg(bp + 1);
            sout[wInB][c0 + 0] = fmaf(accf[0].x, invv, b0.x);
            sout[wInB][c0 + 1] = fmaf(accf[0].y, invv, b0.y);
            sout[wInB][c0 + 2] = fmaf(accf[1].x, invv, b0.z);
            sout[wInB][c0 + 3] = fmaf(accf[1].y, invv, b0.w);
            sout[wInB][c0 + 4] = fmaf(accf[2].x, invv, b1.x);
            sout[wInB][c0 + 5] = fmaf(accf[2].y, invv, b1.y);
            sout[wInB][c0 + 6] = fmaf(accf[3].x, invv, b1.z);
            sout[wInB][c0 + 7] = fmaf(accf[3].y, invv, b1.w);
        }
    }
    __syncwarp();
    if (gw < n) {
        for (int d = lane; d < 40; d += 32) {
            float s_ = 0.f;
            #pragma unroll
            for (int hh = 0; hh < 6; ++hh) s_ += sout[wInB][hh * 40 + d];
            logits[(size_t)gw * 40 + d] = s_ * (1.0f / 6.0f) + __ldg(&r2m[(size_t)gw * 40 + d]);
        }
    }
}

// ---------------- host ----------------
extern "C" void kernel_launch(void* const* d_in, const int* in_sizes, int n_in,
                              void* d_out, int out_size)
{
    const float* feat  = (const float*)d_in[0];
    const int*   src   = (const int*)d_in[1];
    const int*   dst   = (const int*)d_in[2];
    const float* W0    = (const float*)d_in[3];
    const float* al0   = (const float*)d_in[4];
    const float* ar0   = (const float*)d_in[5];
    const float* b0    = (const float*)d_in[6];
    const float* W1    = (const float*)d_in[7];
    const float* al1   = (const float*)d_in[8];
    const float* ar1   = (const float*)d_in[9];
    const float* b1    = (const float*)d_in[10];
    const float* W2    = (const float*)d_in[11];
    const float* al2   = (const float*)d_in[12];
    const float* ar2   = (const float*)d_in[13];
    const float* b2    = (const float*)d_in[14];
    const float* resW2 = (const float*)d_in[15];

    const int n = NNODES;
    const int E = in_sizes[1];

    float* logits = (float*)d_out;
    float* h1     = (float*)d_out + n * 40;

    float *pr2, *pelA, *perA, *pelB, *perB;
    __half *pzh, *pAh;
    int* pdeg;
    cudaGetSymbolAddress((void**)&pzh,  g_zh);
    cudaGetSymbolAddress((void**)&pr2,  g_r2);
    cudaGetSymbolAddress((void**)&pelA, g_elA);
    cudaGetSymbolAddress((void**)&perA, g_erA);
    cudaGetSymbolAddress((void**)&pelB, g_elB);
    cudaGetSymbolAddress((void**)&perB, g_erB);
    cudaGetSymbolAddress((void**)&pAh,  g_Ah);
    cudaGetSymbolAddress((void**)&pdeg, g_deg);

    cudaFuncSetAttribute(k_gemm0, cudaFuncAttributeMaxDynamicSharedMemorySize, GEMM_SMEM128);
    cudaFuncSetAttribute(k_gemm1, cudaFuncAttributeMaxDynamicSharedMemorySize, GEMM_SMEM128);
    cudaFuncSetAttribute(k_gemm2, cudaFuncAttributeMaxDynamicSharedMemorySize, GEMM_SMEM128);

    const int nGemm = ((n + 63) / 64) * 2;
    const int nGemmM = (n + 63) / 64;
    const int histBlocks = (E + 255) / 256;
    const int scatBlocks = (E + 127) / 128;
    const int zeroBlocks = (n * 6 + 255) / 256;
    const int aggBlocks  = (n + 7) / 8;

    cudaMemsetAsync(pdeg, 0, n * sizeof(int));
    k_prep0<<<SPLITA_BLOCKS + 256 + histBlocks, 256>>>(feat, W0, dst, E);
    k_scan<<<1, 1024>>>(n, E);
    k_gemm0<<<nGemm + scatBlocks, 128, GEMM_SMEM128>>>(pAh, pzh, al0, ar0, pelA, perA,
                                                       n, nGemm, src, dst, E);
    k_agg256<false><<<aggBlocks + 256, 256>>>(
        pzh, pelA, perA, b0, nullptr, pAh, n, aggBlocks,
        W1, 256, nullptr, nullptr, nullptr, 0);
    k_gemm1<<<nGemm, 128, GEMM_SMEM128>>>(pAh, pzh, al1, ar1, pelB, perB, n);
    k_agg256<true><<<aggBlocks + 256 + 64 + zeroBlocks, 256>>>(
        pzh, pelB, perB, b1, h1, pAh, n, aggBlocks,
        W2, 240, resW2, pelA, perA, n * 6);
    k_gemm2<<<nGemm + nGemmM, 128, GEMM_SMEM128>>>(pAh, pzh, pr2, al2, ar2, pelA, perA,
                                                   n, nGemm);
    k_agg_l2<<<aggBlocks, 256>>>(pzh, pelA, perA, b2, pr2, logits, n);
}